// round 15
// baseline (speedup 1.0000x reference)
#include <cuda_runtime.h>

typedef unsigned long long ull;

#define NB   2
#define CC   256
#define NHD  8
#define HD   32
#define HW   1024
#define WS2  225
#define INVT 0.17677669529663687f

// attention smem layout (floats)
#define JSTR   772                 // arena row stride
#define AR_QSD 24704               // Q dup pairs [c][x], float2 stride 34 (8704 B)
#define AR_ASH 29056               // ash [s][x] stride 36
#define AR_BRK 37156               // brk 225 (pad 240)
#define AR_RVS 37396               // rel_v staged [s][c] stride 36
#define SM_FLOATS 45496
#define ATTN_SMEM (SM_FLOATS*4)    // 181984 B

// Scratch (device globals; allocation-free)
__device__ float g_qT[NB*NHD*HW*HD];   // [nh][p][c]
__device__ float g_kT[NB*NHD*HW*HD];   // [nh][p][c]  (pre-scaled by 1/T)
__device__ float g_vT[NB*NHD*HW*HD];   // [nh][p][c]
__device__ float g_O[CC*NB*HW];        // [c][r], r = p*NB + n
__device__ float g_attn_fallback[NB*NHD*WS2*HW];
__device__ int   g_relv_nz;

// ---- f32x2 helpers -------------------------------------------------------
__device__ __forceinline__ ull pk2(float a, float b) {
    ull r; asm("mov.b64 %0, {%1, %2};" : "=l"(r) : "f"(a), "f"(b)); return r;
}
__device__ __forceinline__ void fma2(ull& d, ull a, ull b) {
    asm("fma.rn.f32x2 %0, %1, %2, %3;" : "=l"(d) : "l"(a), "l"(b), "l"(d));
}
__device__ __forceinline__ float2 upk(ull a) {
    float2 f; asm("mov.b64 {%0, %1}, %2;" : "=f"(f.x), "=f"(f.y) : "l"(a)); return f;
}

// ---------------------------------------------------------------------------
__global__ void relv_flag_kernel(const float* __restrict__ rel_v) {
    const float4* rv4 = (const float4*)rel_v;
    const int total4 = NHD*HD*WS2/4;
    int nz = 0;
    for (int i = threadIdx.x; i < total4; i += blockDim.x) {
        float4 f = rv4[i];
        nz |= (f.x != 0.f) | (f.y != 0.f) | (f.z != 0.f) | (f.w != 0.f);
    }
    int any = __syncthreads_or(nz);
    if (threadIdx.x == 0) g_relv_nz = any;
}

// ---------------------------------------------------------------------------
// Q/K/V projections. Tile 32o x 32p, 128 threads, microtile 4o x 2p (f32x2).
// W stored as DUPLICATED float2 pairs in smem -> no per-iter pack MOVs.
// grid (32 p-tiles, 8 o-tiles, 6 = {q,k,v} x {n}) = 1536 blocks.
// ---------------------------------------------------------------------------
__global__ __launch_bounds__(128) void proj_kernel(
    const float* __restrict__ q, const float* __restrict__ k, const float* __restrict__ v,
    const float* __restrict__ WQ, const float* __restrict__ bQ,
    const float* __restrict__ WK, const float* __restrict__ bK,
    const float* __restrict__ WV, const float* __restrict__ bV)
{
    __shared__ float  Xs[64*32];     // [c][p]  8 KB
    __shared__ float2 Wsd[64*34];    // [c][o] dup pairs, stride 34 -> 17.4 KB

    int which = blockIdx.z >> 1;
    int n     = blockIdx.z & 1;
    const float *X, *W, *B; float* out; float scale;
    if (which == 0)      { X = q; W = WQ; B = bQ; out = g_qT; scale = 1.0f; }
    else if (which == 1) { X = k; W = WK; B = bK; out = g_kT; scale = INVT; }
    else                 { X = v; W = WV; B = bV; out = g_vT; scale = 1.0f; }
    X   += (size_t)n * CC * HW;
    out += (size_t)n * NHD * HW * HD;

    int tid = threadIdx.x;
    int to = tid >> 4;            // 0..7  (o quad: 4 outputs)
    int tp = tid & 15;            // 0..15 (p pair)
    int p0 = blockIdx.x * 32;
    int o0 = blockIdx.y * 32;

    ull acc0 = 0ULL, acc1 = 0ULL, acc2 = 0ULL, acc3 = 0ULL;

    for (int ck = 0; ck < CC; ck += 64) {
        #pragma unroll
        for (int i = 0; i < 4; i++) {
            int idx = tid + i*128;
            int c = idx >> 3, pp = (idx & 7) * 4;
            *(float4*)&Xs[c*32 + pp] = *(const float4*)&X[(size_t)(ck + c)*HW + p0 + pp];
        }
        #pragma unroll
        for (int i = 0; i < 4; i++) {
            int idx = tid + i*128;
            int o = idx >> 4, c4 = (idx & 15) * 4;
            float4 w = *(const float4*)&W[(size_t)(o0 + o)*CC + ck + c4];
            Wsd[(c4+0)*34 + o] = make_float2(w.x*scale, w.x*scale);
            Wsd[(c4+1)*34 + o] = make_float2(w.y*scale, w.y*scale);
            Wsd[(c4+2)*34 + o] = make_float2(w.z*scale, w.z*scale);
            Wsd[(c4+3)*34 + o] = make_float2(w.w*scale, w.w*scale);
        }
        __syncthreads();
        #pragma unroll 8
        for (int c = 0; c < 64; c++) {
            ulonglong2 w01 = *(const ulonglong2*)&Wsd[c*34 + to*4];
            ulonglong2 w23 = *(const ulonglong2*)&Wsd[c*34 + to*4 + 2];
            ull xv = *(const ull*)&Xs[c*32 + tp*2];
            fma2(acc0, w01.x, xv); fma2(acc1, w01.y, xv);
            fma2(acc2, w23.x, xv); fma2(acc3, w23.y, xv);
        }
        __syncthreads();
    }

    float bb0 = B[o0 + to*4 + 0] * scale;
    float bb1 = B[o0 + to*4 + 1] * scale;
    float bb2 = B[o0 + to*4 + 2] * scale;
    float bb3 = B[o0 + to*4 + 3] * scale;
    float2 r0 = upk(acc0), r1 = upk(acc1), r2 = upk(acc2), r3 = upk(acc3);
    int oo = o0 + to*4;
    int h = oo >> 5, c0 = oo & 31;
    int p = p0 + tp*2;
    *(float4*)&out[((size_t)h*HW + p    )*HD + c0] = make_float4(r0.x+bb0, r1.x+bb1, r2.x+bb2, r3.x+bb3);
    *(float4*)&out[((size_t)h*HW + p + 1)*HD + c0] = make_float4(r0.y+bb0, r1.y+bb1, r2.y+bb2, r3.y+bb3);
}

// ---------------------------------------------------------------------------
// Local attention, one block per (y, h, n). 512 threads (16 warps).
// Phase 1: C[32x768] = Q[32x32] x R^T, thread = 4 x-rows x 12 j-cols.
//          Q pre-duplicated in smem (qsd) -> no pack MOVs in the hot loop.
// Phase 2: band-gather + softmax (16 thr/pixel).
// Phase 3: attn.V, tap-rows split across two 8-warp halves, smem combine.
// ---------------------------------------------------------------------------
__global__ __launch_bounds__(512) void attn_kernel(
    const float* __restrict__ Wrk, const float* __restrict__ brk,
    const float* __restrict__ rel_v, float* __restrict__ attn_out)
{
    extern __shared__ float sm[];
    float*  arena = sm;                       // R [c][j] -> qk [x][j] -> V [jj][c]
    float2* qsd   = (float2*)(sm + AR_QSD);   // [c][x] dup pairs, stride 34
    float*  ashp  = sm + AR_ASH;              // [s][x] stride 36
    float*  brks  = sm + AR_BRK;
    float*  rvs   = sm + AR_RVS;              // [s][c] stride 36

    if (attn_out == nullptr) attn_out = g_attn_fallback;

    int y = blockIdx.x, h = blockIdx.y, n = blockIdx.z;
    int nh = n*NHD + h;
    int tid = threadIdx.x;
    int flag = g_relv_nz;

    const float* qbase = g_qT + ((size_t)nh*HW + (size_t)y*32)*HD;
    const float* kbase = g_kT + (size_t)nh*HW*HD;
    const float* vbase = g_vT + (size_t)nh*HW*HD;

    // Q dup pairs [c][x]
    if (tid < 256) {
        int x = tid >> 3, c4 = (tid & 7) * 4;
        float4 f = *(const float4*)&qbase[x*HD + c4];
        qsd[(c4+0)*34 + x] = make_float2(f.x, f.x);
        qsd[(c4+1)*34 + x] = make_float2(f.y, f.y);
        qsd[(c4+2)*34 + x] = make_float2(f.z, f.z);
        qsd[(c4+3)*34 + x] = make_float2(f.w, f.w);
    }
    // R: K-neighborhood columns j = r*32+xx (zero for invalid rows)
    for (int i = tid; i < 480*8; i += 512) {
        int j = i >> 3, c4 = (i & 7) * 4;
        int r = j >> 5, xx = j & 31;
        int gy = y + r - 7;
        float4 f = make_float4(0.f, 0.f, 0.f, 0.f);
        if ((unsigned)gy < 32u) f = *(const float4*)&kbase[(size_t)(gy*32 + xx)*HD + c4];
        arena[(c4+0)*JSTR + j] = f.x; arena[(c4+1)*JSTR + j] = f.y;
        arena[(c4+2)*JSTR + j] = f.z; arena[(c4+3)*JSTR + j] = f.w;
    }
    // R: Wrk columns j = 480+s
    for (int i = tid; i < WS2*8; i += 512) {
        int s = i >> 3, c4 = (i & 7) * 4;
        float4 f = *(const float4*)&Wrk[((size_t)h*WS2 + s)*HD + c4];
        int j = 480 + s;
        arena[(c4+0)*JSTR + j] = f.x; arena[(c4+1)*JSTR + j] = f.y;
        arena[(c4+2)*JSTR + j] = f.z; arena[(c4+3)*JSTR + j] = f.w;
    }
    if (tid < WS2) brks[tid] = brk[h*WS2 + tid];
    __syncthreads();

    // ---- phase 1 GEMM: tx = 4 x-rows (tid>>6), tj = 12 j-cols (tid&63) ----
    int tx = tid >> 6;       // 0..7
    int tj = tid & 63;       // 0..63
    ull acc[4][6];
    #pragma unroll
    for (int a = 0; a < 4; a++)
        #pragma unroll
        for (int b2 = 0; b2 < 6; b2++) acc[a][b2] = 0ULL;

    #pragma unroll 4
    for (int c = 0; c < 32; c++) {
        ulonglong2 q01 = *(const ulonglong2*)&qsd[c*34 + tx*4];
        ulonglong2 q23 = *(const ulonglong2*)&qsd[c*34 + tx*4 + 2];
        const float* rb = &arena[c*JSTR + tj*4];
        #pragma unroll
        for (int cc = 0; cc < 3; cc++) {
            ulonglong2 rr = *(const ulonglong2*)(rb + cc*256);
            fma2(acc[0][cc*2+0], q01.x, rr.x); fma2(acc[0][cc*2+1], q01.x, rr.y);
            fma2(acc[1][cc*2+0], q01.y, rr.x); fma2(acc[1][cc*2+1], q01.y, rr.y);
            fma2(acc[2][cc*2+0], q23.x, rr.x); fma2(acc[2][cc*2+1], q23.x, rr.y);
            fma2(acc[3][cc*2+0], q23.y, rr.x); fma2(acc[3][cc*2+1], q23.y, rr.y);
        }
    }
    __syncthreads();
    // write qk into arena rows [x][j]
    #pragma unroll
    for (int xi = 0; xi < 4; xi++) {
        float* row = &arena[(tx*4 + xi)*JSTR + tj*4];
        #pragma unroll
        for (int cc = 0; cc < 3; cc++) {
            ulonglong2 v; v.x = acc[xi][cc*2+0]; v.y = acc[xi][cc*2+1];
            *(ulonglong2*)(row + cc*256) = v;
        }
    }
    __syncthreads();

    // ---- softmax over 225 taps, 16 threads per pixel ----
    {
        int sx = tid >> 4, sub = tid & 15;
        const float* qrow = &arena[sx*JSTR];
        float m = -3.0e38f;
        for (int s = sub; s < WS2; s += 16) {
            int r = s / 15, dx = s - r*15;
            int xx = sx + dx - 7, gy = y + r - 7;
            float val = -1.0e8f;
            if ((unsigned)xx < 32u && (unsigned)gy < 32u)
                val = qrow[r*32 + xx] + qrow[480 + s] + brks[s];
            ashp[s*36 + sx] = val;
            m = fmaxf(m, val);
        }
        m = fmaxf(m, __shfl_xor_sync(0xffffffffu, m, 1));
        m = fmaxf(m, __shfl_xor_sync(0xffffffffu, m, 2));
        m = fmaxf(m, __shfl_xor_sync(0xffffffffu, m, 4));
        m = fmaxf(m, __shfl_xor_sync(0xffffffffu, m, 8));
        float lsum = 0.f;
        for (int s = sub; s < WS2; s += 16) {
            float e = __expf(ashp[s*36 + sx] - m);
            ashp[s*36 + sx] = e;
            lsum += e;
        }
        lsum += __shfl_xor_sync(0xffffffffu, lsum, 1);
        lsum += __shfl_xor_sync(0xffffffffu, lsum, 2);
        lsum += __shfl_xor_sync(0xffffffffu, lsum, 4);
        lsum += __shfl_xor_sync(0xffffffffu, lsum, 8);
        float rinv = 1.0f / lsum;
        for (int s = sub; s < WS2; s += 16) ashp[s*36 + sx] *= rinv;
    }
    __syncthreads();

    // ---- attn global write + V fill (arena reuse, +7 zero-padded rows) ----
    {
        float* aout = attn_out + (size_t)nh*WS2*HW + y*32;
        for (int i = tid; i < WS2*32; i += 512) {
            int s = i >> 5, x2 = i & 31;
            aout[(size_t)s*HW + x2] = ashp[s*36 + x2];
        }
    }
    for (int i = tid; i < 494*8; i += 512) {
        int jj = i >> 3, c4 = (i & 7) * 4;
        float4 f = make_float4(0.f, 0.f, 0.f, 0.f);
        if (jj >= 7 && jj < 487) {
            int j = jj - 7;
            int r = j >> 5, xx = j & 31;
            int gy = y + r - 7;
            if ((unsigned)gy < 32u) f = *(const float4*)&vbase[(size_t)(gy*32 + xx)*HD + c4];
        }
        *(float4*)&arena[jj*36 + c4] = f;
    }
    if (flag) {
        for (int i = tid; i < HD*WS2; i += 512) {
            int c = i / WS2, s = i - c*WS2;
            rvs[s*36 + c] = rel_v[((size_t)h*HD + c)*WS2 + s];
        }
    }
    __syncthreads();

    // ---- pass B: out[c] = sum_taps a * v, split across two 8-warp halves ----
    {
        int xb  = tid & 31;
        int g   = tid >> 5;            // 0..15
        int cgi = g & 7;               // channel group (4 channels)
        int cg4 = cgi * 4;
        int half = g >> 3;             // 0 or 1
        ull a0 = 0ULL, a1 = 0ULL;

        int r_begin = half ? 8 : 0;
        int r_end   = half ? 15 : 8;
        for (int r = r_begin; r < r_end; r++) {
            int gy = y + r - 7;
            if ((unsigned)gy >= 32u) continue;
            const float* ap = &ashp[(r*15)*36 + xb];
            const float* vp = &arena[(r*32 + xb)*36 + cg4];
            #pragma unroll
            for (int dx = 0; dx < 15; dx++) {
                float a = ap[dx*36];
                ull a2 = pk2(a, a);
                ulonglong2 vv = *(const ulonglong2*)(vp + dx*36);
                fma2(a0, a2, vv.x); fma2(a1, a2, vv.y);
            }
        }
        if (flag) {
            int s0 = half ? 112 : 0, s1 = half ? 225 : 112;
            for (int s = s0; s < s1; s++) {
                float a = ashp[s*36 + xb];
                ull a2 = pk2(a, a);
                ulonglong2 rv = *(const ulonglong2*)&rvs[s*36 + cg4];
                fma2(a0, a2, rv.x); fma2(a1, a2, rv.y);
            }
        }
        float* part = sm + AR_QSD;   // reuse Q-dup region: 1024 floats needed
        if (half) {
            ulonglong2 v; v.x = a0; v.y = a1;
            *(ulonglong2*)&part[(cgi*32 + xb)*4] = v;
        }
        __syncthreads();
        if (!half) {
            ulonglong2 pv = *(const ulonglong2*)&part[(cgi*32 + xb)*4];
            float2 p01 = upk(pv.x), p23 = upk(pv.y);
            float2 o01 = upk(a0),  o23 = upk(a1);
            o01.x += p01.x; o01.y += p01.y; o23.x += p23.x; o23.y += p23.y;
            int cfull = h*HD + cg4;
            int rr = (y*32 + xb)*NB + n;
            g_O[(size_t)(cfull+0)*(NB*HW) + rr] = o01.x;
            g_O[(size_t)(cfull+1)*(NB*HW) + rr] = o01.y;
            g_O[(size_t)(cfull+2)*(NB*HW) + rr] = o23.x;
            g_O[(size_t)(cfull+3)*(NB*HW) + rr] = o23.y;
        }
    }
}

// ---------------------------------------------------------------------------
// Final projection: tile 32o x 32r, 128 threads, 4o x 2r microtile, dup-W.
// grid (64 r-tiles, 8 o-tiles) = 512 blocks.
// ---------------------------------------------------------------------------
__global__ __launch_bounds__(128) void final_kernel(
    const float* __restrict__ Wp, const float* __restrict__ bp, float* __restrict__ outp)
{
    __shared__ float  Xs[64*32];     // [c][r]
    __shared__ float2 Wsd[64*34];    // [c][o] dup pairs
    const int R = NB*HW;

    int tid = threadIdx.x;
    int to = tid >> 4;
    int tp = tid & 15;
    int r0 = blockIdx.x * 32;
    int o0 = blockIdx.y * 32;

    ull acc0 = 0ULL, acc1 = 0ULL, acc2 = 0ULL, acc3 = 0ULL;

    for (int ck = 0; ck < CC; ck += 64) {
        #pragma unroll
        for (int i = 0; i < 4; i++) {
            int idx = tid + i*128;
            int c = idx >> 3, pp = (idx & 7) * 4;
            *(float4*)&Xs[c*32 + pp] = *(const float4*)&g_O[(size_t)(ck + c)*R + r0 + pp];
        }
        #pragma unroll
        for (int i = 0; i < 4; i++) {
            int idx = tid + i*128;
            int o = idx >> 4, c4 = (idx & 15) * 4;
            float4 w = *(const float4*)&Wp[(size_t)(o0 + o)*CC + ck + c4];
            Wsd[(c4+0)*34 + o] = make_float2(w.x, w.x);
            Wsd[(c4+1)*34 + o] = make_float2(w.y, w.y);
            Wsd[(c4+2)*34 + o] = make_float2(w.z, w.z);
            Wsd[(c4+3)*34 + o] = make_float2(w.w, w.w);
        }
        __syncthreads();
        #pragma unroll 8
        for (int c = 0; c < 64; c++) {
            ulonglong2 w01 = *(const ulonglong2*)&Wsd[c*34 + to*4];
            ulonglong2 w23 = *(const ulonglong2*)&Wsd[c*34 + to*4 + 2];
            ull xv = *(const ull*)&Xs[c*32 + tp*2];
            fma2(acc0, w01.x, xv); fma2(acc1, w01.y, xv);
            fma2(acc2, w23.x, xv); fma2(acc3, w23.y, xv);
        }
        __syncthreads();
    }

    float bb0 = bp[o0 + to*4 + 0];
    float bb1 = bp[o0 + to*4 + 1];
    float bb2 = bp[o0 + to*4 + 2];
    float bb3 = bp[o0 + to*4 + 3];
    float2 r0v = upk(acc0), r1v = upk(acc1), r2v = upk(acc2), r3v = upk(acc3);
    int oo = o0 + to*4;
    int r = r0 + tp*2;
    *(float4*)&outp[(size_t)(r    )*CC + oo] = make_float4(r0v.x+bb0, r1v.x+bb1, r2v.x+bb2, r3v.x+bb3);
    *(float4*)&outp[(size_t)(r + 1)*CC + oo] = make_float4(r0v.y+bb0, r1v.y+bb1, r2v.y+bb2, r3v.y+bb3);
}

// ---------------------------------------------------------------------------
extern "C" void kernel_launch(void* const* d_in, const int* in_sizes, int n_in,
                              void* d_out, int out_size)
{
    const float* q     = (const float*)d_in[0];
    const float* k     = (const float*)d_in[1];
    const float* v     = (const float*)d_in[2];
    const float* WQ    = (const float*)d_in[3];
    const float* bQ    = (const float*)d_in[4];
    const float* WK    = (const float*)d_in[5];
    const float* bK    = (const float*)d_in[6];
    const float* WV    = (const float*)d_in[7];
    const float* bV    = (const float*)d_in[8];
    const float* Wrk   = (const float*)d_in[9];
    const float* brk   = (const float*)d_in[10];
    const float* rel_v = (const float*)d_in[11];
    const float* Wp    = (const float*)d_in[12];
    const float* bp    = (const float*)d_in[13];

    float* out = (float*)d_out;
    const int OUT_ELEMS  = HW*NB*CC;
    const int ATTN_ELEMS = NB*NHD*WS2*HW;
    float* attn_out = (out_size >= OUT_ELEMS + ATTN_ELEMS) ? (out + OUT_ELEMS) : nullptr;

    cudaFuncSetAttribute(attn_kernel, cudaFuncAttributeMaxDynamicSharedMemorySize, ATTN_SMEM);

    relv_flag_kernel<<<1, 1024>>>(rel_v);
    proj_kernel<<<dim3(32, 8, 6), 128>>>(q, k, v, WQ, bQ, WK, bK, WV, bV);
    attn_kernel<<<dim3(32, NHD, NB), 512, ATTN_SMEM>>>(Wrk, brk, rel_v, attn_out);
    final_kernel<<<dim3(64, 8), 128>>>(Wp, bp, out);
}

// round 16
// speedup vs baseline: 1.1291x; 1.1291x over previous
#include <cuda_runtime.h>

typedef unsigned long long ull;

#define NB   2
#define CC   256
#define NHD  8
#define HD   32
#define HW   1024
#define WS2  225
#define INVT 0.17677669529663687f

// attention smem layout (floats) — identical to the 137.7us-measured version
#define JSTR   772
#define AR_QS  24704
#define AR_ASH 25856
#define AR_BRK 33956
#define AR_RVS 34196
#define SM_FLOATS 42296
#define ATTN_SMEM (SM_FLOATS*4)    // 169184 B

__device__ float g_qT[NB*NHD*HW*HD];   // [nh][p][c]
__device__ float g_kT[NB*NHD*HW*HD];   // [nh][p][c]  (pre-scaled by 1/T)
__device__ float g_vT[NB*NHD*HW*HD];   // [nh][p][c]
__device__ float g_O[CC*NB*HW];        // [c][r], r = p*NB + n
__device__ float g_attn_fallback[NB*NHD*WS2*HW];
__device__ int   g_relv_nz;

__device__ __forceinline__ ull pk2(float a, float b) {
    ull r; asm("mov.b64 %0, {%1, %2};" : "=l"(r) : "f"(a), "f"(b)); return r;
}
__device__ __forceinline__ void fma2(ull& d, ull a, ull b) {
    asm("fma.rn.f32x2 %0, %1, %2, %3;" : "=l"(d) : "l"(a), "l"(b), "l"(d));
}
__device__ __forceinline__ float2 upk(ull a) {
    float2 f; asm("mov.b64 {%0, %1}, %2;" : "=f"(f.x), "=f"(f.y) : "l"(a)); return f;
}

// ---------------------------------------------------------------------------
__global__ void relv_flag_kernel(const float* __restrict__ rel_v) {
    const float4* rv4 = (const float4*)rel_v;
    const int total4 = NHD*HD*WS2/4;
    int nz = 0;
    for (int i = threadIdx.x; i < total4; i += blockDim.x) {
        float4 f = rv4[i];
        nz |= (f.x != 0.f) | (f.y != 0.f) | (f.z != 0.f) | (f.w != 0.f);
    }
    int any = __syncthreads_or(nz);
    if (threadIdx.x == 0) g_relv_nz = any;
}

// ---------------------------------------------------------------------------
// GEMM core layout shared by proj/final:
// tile 64o x 64p, 128 threads, microtile 4o x 8p.
// W in smem as duplicated float2 pairs (Wsd[c][o], stride 66 pairs),
// X in smem [c][p] stride 64. Per c: 4x LDS.128 + 16 FFMA2 (fma-bound 2:1).
// ---------------------------------------------------------------------------
__global__ __launch_bounds__(128) void proj_kernel(
    const float* __restrict__ q, const float* __restrict__ k, const float* __restrict__ v,
    const float* __restrict__ WQ, const float* __restrict__ bQ,
    const float* __restrict__ WK, const float* __restrict__ bK,
    const float* __restrict__ WV, const float* __restrict__ bV)
{
    __shared__ float  Xs[64*64];     // [c][p] 16 KB
    __shared__ float2 Wsd[64*66];    // [c][o] dup pairs, 33.8 KB

    int which = blockIdx.z >> 1;
    int n     = blockIdx.z & 1;
    const float *X, *W, *B; float* out; float scale;
    if (which == 0)      { X = q; W = WQ; B = bQ; out = g_qT; scale = 1.0f; }
    else if (which == 1) { X = k; W = WK; B = bK; out = g_kT; scale = INVT; }
    else                 { X = v; W = WV; B = bV; out = g_vT; scale = 1.0f; }
    X   += (size_t)n * CC * HW;
    out += (size_t)n * NHD * HW * HD;

    int tid = threadIdx.x;
    int oo = tid >> 3;            // 0..15 (4 o each)
    int po = tid & 7;             // 0..7  (8 p each)
    int p0 = blockIdx.x * 64;
    int o0 = blockIdx.y * 64;

    ull acc[4][4];
    #pragma unroll
    for (int a = 0; a < 4; a++)
        #pragma unroll
        for (int b2 = 0; b2 < 4; b2++) acc[a][b2] = 0ULL;

    for (int ck = 0; ck < CC; ck += 64) {
        #pragma unroll
        for (int i = 0; i < 8; i++) {
            int idx = tid + i*128;
            int c = idx >> 4, pp = (idx & 15) * 4;
            *(float4*)&Xs[c*64 + pp] = *(const float4*)&X[(size_t)(ck + c)*HW + p0 + pp];
        }
        #pragma unroll
        for (int i = 0; i < 8; i++) {
            int idx = tid + i*128;
            int o = idx >> 4, c4 = (idx & 15) * 4;
            float4 w = *(const float4*)&W[(size_t)(o0 + o)*CC + ck + c4];
            Wsd[(c4+0)*66 + o] = make_float2(w.x*scale, w.x*scale);
            Wsd[(c4+1)*66 + o] = make_float2(w.y*scale, w.y*scale);
            Wsd[(c4+2)*66 + o] = make_float2(w.z*scale, w.z*scale);
            Wsd[(c4+3)*66 + o] = make_float2(w.w*scale, w.w*scale);
        }
        __syncthreads();
        #pragma unroll 4
        for (int c = 0; c < 64; c++) {
            ulonglong2 wA = *(const ulonglong2*)&Wsd[c*66 + oo*4];      // o+0, o+1
            ulonglong2 wB = *(const ulonglong2*)&Wsd[c*66 + oo*4 + 2];  // o+2, o+3
            ulonglong2 xA = *(const ulonglong2*)&Xs[c*64 + po*8];       // p 0-3
            ulonglong2 xB = *(const ulonglong2*)&Xs[c*64 + po*8 + 4];   // p 4-7
            fma2(acc[0][0], wA.x, xA.x); fma2(acc[0][1], wA.x, xA.y);
            fma2(acc[0][2], wA.x, xB.x); fma2(acc[0][3], wA.x, xB.y);
            fma2(acc[1][0], wA.y, xA.x); fma2(acc[1][1], wA.y, xA.y);
            fma2(acc[1][2], wA.y, xB.x); fma2(acc[1][3], wA.y, xB.y);
            fma2(acc[2][0], wB.x, xA.x); fma2(acc[2][1], wB.x, xA.y);
            fma2(acc[2][2], wB.x, xB.x); fma2(acc[2][3], wB.x, xB.y);
            fma2(acc[3][0], wB.y, xA.x); fma2(acc[3][1], wB.y, xA.y);
            fma2(acc[3][2], wB.y, xB.x); fma2(acc[3][3], wB.y, xB.y);
        }
        __syncthreads();
    }

    // epilogue: res[o][p] for 4 o x 8 p
    float res[4][8];
    #pragma unroll
    for (int a = 0; a < 4; a++) {
        float bb = B[o0 + oo*4 + a] * scale;
        #pragma unroll
        for (int j = 0; j < 4; j++) {
            float2 pr = upk(acc[a][j]);
            res[a][2*j+0] = pr.x + bb;
            res[a][2*j+1] = pr.y + bb;
        }
    }
    int obase = o0 + oo*4;
    int h = obase >> 5, c0 = obase & 31;
    #pragma unroll
    for (int kk = 0; kk < 8; kk++) {
        int p = p0 + po*8 + kk;
        float4 f4 = make_float4(res[0][kk], res[1][kk], res[2][kk], res[3][kk]);
        *(float4*)&out[((size_t)h*HW + p)*HD + c0] = f4;
    }
}

// ---------------------------------------------------------------------------
// Local attention — identical to the 137.7us-measured version.
// One block per (y, h, n), 512 threads.
// ---------------------------------------------------------------------------
__global__ __launch_bounds__(512) void attn_kernel(
    const float* __restrict__ Wrk, const float* __restrict__ brk,
    const float* __restrict__ rel_v, float* __restrict__ attn_out)
{
    extern __shared__ float sm[];
    float* arena = sm;
    float* qs    = sm + AR_QS;
    float* ashp  = sm + AR_ASH;
    float* brks  = sm + AR_BRK;
    float* rvs   = sm + AR_RVS;

    if (attn_out == nullptr) attn_out = g_attn_fallback;

    int y = blockIdx.x, h = blockIdx.y, n = blockIdx.z;
    int nh = n*NHD + h;
    int tid = threadIdx.x;
    int flag = g_relv_nz;

    const float* qbase = g_qT + ((size_t)nh*HW + (size_t)y*32)*HD;
    const float* kbase = g_kT + (size_t)nh*HW*HD;
    const float* vbase = g_vT + (size_t)nh*HW*HD;

    if (tid < 256) {
        int x = tid >> 3, c4 = (tid & 7) * 4;
        float4 f = *(const float4*)&qbase[x*HD + c4];
        qs[(c4+0)*36 + x] = f.x; qs[(c4+1)*36 + x] = f.y;
        qs[(c4+2)*36 + x] = f.z; qs[(c4+3)*36 + x] = f.w;
    }
    for (int i = tid; i < 480*8; i += 512) {
        int j = i >> 3, c4 = (i & 7) * 4;
        int r = j >> 5, xx = j & 31;
        int gy = y + r - 7;
        float4 f = make_float4(0.f, 0.f, 0.f, 0.f);
        if ((unsigned)gy < 32u) f = *(const float4*)&kbase[(size_t)(gy*32 + xx)*HD + c4];
        arena[(c4+0)*JSTR + j] = f.x; arena[(c4+1)*JSTR + j] = f.y;
        arena[(c4+2)*JSTR + j] = f.z; arena[(c4+3)*JSTR + j] = f.w;
    }
    for (int i = tid; i < WS2*8; i += 512) {
        int s = i >> 3, c4 = (i & 7) * 4;
        float4 f = *(const float4*)&Wrk[((size_t)h*WS2 + s)*HD + c4];
        int j = 480 + s;
        arena[(c4+0)*JSTR + j] = f.x; arena[(c4+1)*JSTR + j] = f.y;
        arena[(c4+2)*JSTR + j] = f.z; arena[(c4+3)*JSTR + j] = f.w;
    }
    if (tid < WS2) brks[tid] = brk[h*WS2 + tid];
    __syncthreads();

    int tx = tid >> 6;       // 0..7
    int tj = tid & 63;       // 0..63
    ull acc[4][6];
    #pragma unroll
    for (int a = 0; a < 4; a++)
        #pragma unroll
        for (int b2 = 0; b2 < 6; b2++) acc[a][b2] = 0ULL;

    #pragma unroll 4
    for (int c = 0; c < 32; c++) {
        float4 qv = *(const float4*)&qs[c*36 + tx*4];
        ull q0 = pk2(qv.x, qv.x), q1 = pk2(qv.y, qv.y);
        ull q2 = pk2(qv.z, qv.z), q3 = pk2(qv.w, qv.w);
        const float* rb = &arena[c*JSTR + tj*4];
        #pragma unroll
        for (int cc = 0; cc < 3; cc++) {
            ulonglong2 rr = *(const ulonglong2*)(rb + cc*256);
            fma2(acc[0][cc*2+0], q0, rr.x); fma2(acc[0][cc*2+1], q0, rr.y);
            fma2(acc[1][cc*2+0], q1, rr.x); fma2(acc[1][cc*2+1], q1, rr.y);
            fma2(acc[2][cc*2+0], q2, rr.x); fma2(acc[2][cc*2+1], q2, rr.y);
            fma2(acc[3][cc*2+0], q3, rr.x); fma2(acc[3][cc*2+1], q3, rr.y);
        }
    }
    __syncthreads();
    #pragma unroll
    for (int xi = 0; xi < 4; xi++) {
        float* row = &arena[(tx*4 + xi)*JSTR + tj*4];
        #pragma unroll
        for (int cc = 0; cc < 3; cc++) {
            ulonglong2 v; v.x = acc[xi][cc*2+0]; v.y = acc[xi][cc*2+1];
            *(ulonglong2*)(row + cc*256) = v;
        }
    }
    __syncthreads();

    {
        int sx = tid >> 4, sub = tid & 15;
        const float* qrow = &arena[sx*JSTR];
        float m = -3.0e38f;
        for (int s = sub; s < WS2; s += 16) {
            int r = s / 15, dx = s - r*15;
            int xx = sx + dx - 7, gy = y + r - 7;
            float val = -1.0e8f;
            if ((unsigned)xx < 32u && (unsigned)gy < 32u)
                val = qrow[r*32 + xx] + qrow[480 + s] + brks[s];
            ashp[s*36 + sx] = val;
            m = fmaxf(m, val);
        }
        m = fmaxf(m, __shfl_xor_sync(0xffffffffu, m, 1));
        m = fmaxf(m, __shfl_xor_sync(0xffffffffu, m, 2));
        m = fmaxf(m, __shfl_xor_sync(0xffffffffu, m, 4));
        m = fmaxf(m, __shfl_xor_sync(0xffffffffu, m, 8));
        float lsum = 0.f;
        for (int s = sub; s < WS2; s += 16) {
            float e = __expf(ashp[s*36 + sx] - m);
            ashp[s*36 + sx] = e;
            lsum += e;
        }
        lsum += __shfl_xor_sync(0xffffffffu, lsum, 1);
        lsum += __shfl_xor_sync(0xffffffffu, lsum, 2);
        lsum += __shfl_xor_sync(0xffffffffu, lsum, 4);
        lsum += __shfl_xor_sync(0xffffffffu, lsum, 8);
        float rinv = 1.0f / lsum;
        for (int s = sub; s < WS2; s += 16) ashp[s*36 + sx] *= rinv;
    }
    __syncthreads();

    {
        float* aout = attn_out + (size_t)nh*WS2*HW + y*32;
        for (int i = tid; i < WS2*32; i += 512) {
            int s = i >> 5, x2 = i & 31;
            aout[(size_t)s*HW + x2] = ashp[s*36 + x2];
        }
    }
    for (int i = tid; i < 494*8; i += 512) {
        int jj = i >> 3, c4 = (i & 7) * 4;
        float4 f = make_float4(0.f, 0.f, 0.f, 0.f);
        if (jj >= 7 && jj < 487) {
            int j = jj - 7;
            int r = j >> 5, xx = j & 31;
            int gy = y + r - 7;
            if ((unsigned)gy < 32u) f = *(const float4*)&vbase[(size_t)(gy*32 + xx)*HD + c4];
        }
        *(float4*)&arena[jj*36 + c4] = f;
    }
    if (flag) {
        for (int i = tid; i < HD*WS2; i += 512) {
            int c = i / WS2, s = i - c*WS2;
            rvs[s*36 + c] = rel_v[((size_t)h*HD + c)*WS2 + s];
        }
    }
    __syncthreads();

    {
        int xb  = tid & 31;
        int g   = tid >> 5;
        int cgi = g & 7;
        int cg4 = cgi * 4;
        int half = g >> 3;
        ull a0 = 0ULL, a1 = 0ULL;

        int r_begin = half ? 8 : 0;
        int r_end   = half ? 15 : 8;
        for (int r = r_begin; r < r_end; r++) {
            int gy = y + r - 7;
            if ((unsigned)gy >= 32u) continue;
            const float* ap = &ashp[(r*15)*36 + xb];
            const float* vp = &arena[(r*32 + xb)*36 + cg4];
            #pragma unroll
            for (int dx = 0; dx < 15; dx++) {
                float a = ap[dx*36];
                ull a2 = pk2(a, a);
                ulonglong2 vv = *(const ulonglong2*)(vp + dx*36);
                fma2(a0, a2, vv.x); fma2(a1, a2, vv.y);
            }
        }
        if (flag) {
            int s0 = half ? 112 : 0, s1 = half ? 225 : 112;
            for (int s = s0; s < s1; s++) {
                float a = ashp[s*36 + xb];
                ull a2 = pk2(a, a);
                ulonglong2 rv = *(const ulonglong2*)&rvs[s*36 + cg4];
                fma2(a0, a2, rv.x); fma2(a1, a2, rv.y);
            }
        }
        float* part = qs;
        if (half) {
            ulonglong2 v; v.x = a0; v.y = a1;
            *(ulonglong2*)&part[(cgi*32 + xb)*4] = v;
        }
        __syncthreads();
        if (!half) {
            ulonglong2 pv = *(const ulonglong2*)&part[(cgi*32 + xb)*4];
            float2 p01 = upk(pv.x), p23 = upk(pv.y);
            float2 o01 = upk(a0),  o23 = upk(a1);
            o01.x += p01.x; o01.y += p01.y; o23.x += p23.x; o23.y += p23.y;
            int cfull = h*HD + cg4;
            int rr = (y*32 + xb)*NB + n;
            g_O[(size_t)(cfull+0)*(NB*HW) + rr] = o01.x;
            g_O[(size_t)(cfull+1)*(NB*HW) + rr] = o01.y;
            g_O[(size_t)(cfull+2)*(NB*HW) + rr] = o23.x;
            g_O[(size_t)(cfull+3)*(NB*HW) + rr] = o23.y;
        }
    }
}

// ---------------------------------------------------------------------------
// Final projection: tile 64o x 64r, 128 threads, 4o x 8r dup-FFMA2 microtile.
// grid (32 r-tiles, 4 o-tiles) = 128 blocks.
// ---------------------------------------------------------------------------
__global__ __launch_bounds__(128) void final_kernel(
    const float* __restrict__ Wp, const float* __restrict__ bp, float* __restrict__ outp)
{
    __shared__ float  Xs[64*64];
    __shared__ float2 Wsd[64*66];
    const int R = NB*HW;

    int tid = threadIdx.x;
    int oo = tid >> 3;
    int po = tid & 7;
    int r0 = blockIdx.x * 64;
    int o0 = blockIdx.y * 64;

    ull acc[4][4];
    #pragma unroll
    for (int a = 0; a < 4; a++)
        #pragma unroll
        for (int b2 = 0; b2 < 4; b2++) acc[a][b2] = 0ULL;

    for (int ck = 0; ck < CC; ck += 64) {
        #pragma unroll
        for (int i = 0; i < 8; i++) {
            int idx = tid + i*128;
            int c = idx >> 4, pp = (idx & 15) * 4;
            *(float4*)&Xs[c*64 + pp] = *(const float4*)&g_O[(size_t)(ck + c)*R + r0 + pp];
        }
        #pragma unroll
        for (int i = 0; i < 8; i++) {
            int idx = tid + i*128;
            int o = idx >> 4, c4 = (idx & 15) * 4;
            float4 w = *(const float4*)&Wp[(size_t)(o0 + o)*CC + ck + c4];
            Wsd[(c4+0)*66 + o] = make_float2(w.x, w.x);
            Wsd[(c4+1)*66 + o] = make_float2(w.y, w.y);
            Wsd[(c4+2)*66 + o] = make_float2(w.z, w.z);
            Wsd[(c4+3)*66 + o] = make_float2(w.w, w.w);
        }
        __syncthreads();
        #pragma unroll 4
        for (int c = 0; c < 64; c++) {
            ulonglong2 wA = *(const ulonglong2*)&Wsd[c*66 + oo*4];
            ulonglong2 wB = *(const ulonglong2*)&Wsd[c*66 + oo*4 + 2];
            ulonglong2 xA = *(const ulonglong2*)&Xs[c*64 + po*8];
            ulonglong2 xB = *(const ulonglong2*)&Xs[c*64 + po*8 + 4];
            fma2(acc[0][0], wA.x, xA.x); fma2(acc[0][1], wA.x, xA.y);
            fma2(acc[0][2], wA.x, xB.x); fma2(acc[0][3], wA.x, xB.y);
            fma2(acc[1][0], wA.y, xA.x); fma2(acc[1][1], wA.y, xA.y);
            fma2(acc[1][2], wA.y, xB.x); fma2(acc[1][3], wA.y, xB.y);
            fma2(acc[2][0], wB.x, xA.x); fma2(acc[2][1], wB.x, xA.y);
            fma2(acc[2][2], wB.x, xB.x); fma2(acc[2][3], wB.x, xB.y);
            fma2(acc[3][0], wB.y, xA.x); fma2(acc[3][1], wB.y, xA.y);
            fma2(acc[3][2], wB.y, xB.x); fma2(acc[3][3], wB.y, xB.y);
        }
        __syncthreads();
    }

    float res[4][8];
    #pragma unroll
    for (int a = 0; a < 4; a++) {
        float bb = bp[o0 + oo*4 + a];
        #pragma unroll
        for (int j = 0; j < 4; j++) {
            float2 pr = upk(acc[a][j]);
            res[a][2*j+0] = pr.x + bb;
            res[a][2*j+1] = pr.y + bb;
        }
    }
    int obase = o0 + oo*4;
    #pragma unroll
    for (int kk = 0; kk < 8; kk++) {
        int r = r0 + po*8 + kk;
        float4 f4 = make_float4(res[0][kk], res[1][kk], res[2][kk], res[3][kk]);
        *(float4*)&outp[(size_t)r*CC + obase] = f4;
    }
}

// ---------------------------------------------------------------------------
extern "C" void kernel_launch(void* const* d_in, const int* in_sizes, int n_in,
                              void* d_out, int out_size)
{
    const float* q     = (const float*)d_in[0];
    const float* k     = (const float*)d_in[1];
    const float* v     = (const float*)d_in[2];
    const float* WQ    = (const float*)d_in[3];
    const float* bQ    = (const float*)d_in[4];
    const float* WK    = (const float*)d_in[5];
    const float* bK    = (const float*)d_in[6];
    const float* WV    = (const float*)d_in[7];
    const float* bV    = (const float*)d_in[8];
    const float* Wrk   = (const float*)d_in[9];
    const float* brk   = (const float*)d_in[10];
    const float* rel_v = (const float*)d_in[11];
    const float* Wp    = (const float*)d_in[12];
    const float* bp    = (const float*)d_in[13];

    float* out = (float*)d_out;
    const int OUT_ELEMS  = HW*NB*CC;
    const int ATTN_ELEMS = NB*NHD*WS2*HW;
    float* attn_out = (out_size >= OUT_ELEMS + ATTN_ELEMS) ? (out + OUT_ELEMS) : nullptr;

    cudaFuncSetAttribute(attn_kernel, cudaFuncAttributeMaxDynamicSharedMemorySize, ATTN_SMEM);

    relv_flag_kernel<<<1, 1024>>>(rel_v);
    proj_kernel<<<dim3(16, 4, 6), 128>>>(q, k, v, WQ, bQ, WK, bK, WV, bV);
    attn_kernel<<<dim3(32, NHD, NB), 512, ATTN_SMEM>>>(Wrk, brk, rel_v, attn_out);
    final_kernel<<<dim3(32, 4), 128>>>(Wp, bp, out);
}